// round 1
// baseline (speedup 1.0000x reference)
#include <cuda_runtime.h>
#include <math.h>

#define B_  2
#define S_  2048
#define E_  1024
#define H_  16
#define HD_ 64

// Scratch (allocation-free: __device__ globals)
__device__ float g_Q[B_*H_*S_*HD_];   // (b,h,s,d), pre-scaled by hd^-0.5
__device__ float g_K[B_*H_*S_*HD_];   // (b,h,s,d)
__device__ float g_V[B_*H_*S_*HD_];   // (b,h,s,d)
__device__ float g_O[B_*S_*E_];       // (b,s,h*d) — attention out, proj input

// ---------------------------------------------------------------------------
// SGEMM core: C[128x128] tile of A[M,1024] @ B[N,1024]^T  (both K-major, K=1024)
// 256 threads, BK=16, 8x8 microtile per thread. Smem stride 132 (pad 4).
// ---------------------------------------------------------------------------
#define GEMM_BODY(APTR, BPTR)                                                  \
    __shared__ float As[16*132];                                               \
    __shared__ float Bs[16*132];                                               \
    const int tid = threadIdx.x;                                               \
    const int m0 = blockIdx.y * 128;                                           \
    const int n0 = blockIdx.x * 128;                                           \
    const int lr = tid >> 2;                                                   \
    const int lk = (tid & 3) << 2;                                             \
    const int tm = (tid >> 4) << 3;                                            \
    const int tn = (tid & 15) << 3;                                            \
    float acc[8][8];                                                           \
    _Pragma("unroll")                                                          \
    for (int i = 0; i < 8; i++)                                                \
        _Pragma("unroll")                                                      \
        for (int j = 0; j < 8; j++) acc[i][j] = 0.f;                           \
    for (int k0 = 0; k0 < 1024; k0 += 16) {                                    \
        _Pragma("unroll")                                                      \
        for (int it = 0; it < 2; ++it) {                                       \
            int r = lr + it * 64;                                              \
            float4 va = *(const float4*)((APTR) + (size_t)(m0 + r) * 1024 + k0 + lk); \
            As[(lk+0)*132 + r] = va.x;                                         \
            As[(lk+1)*132 + r] = va.y;                                         \
            As[(lk+2)*132 + r] = va.z;                                         \
            As[(lk+3)*132 + r] = va.w;                                         \
            float4 vb = *(const float4*)((BPTR) + (size_t)(n0 + r) * 1024 + k0 + lk); \
            Bs[(lk+0)*132 + r] = vb.x;                                         \
            Bs[(lk+1)*132 + r] = vb.y;                                         \
            Bs[(lk+2)*132 + r] = vb.z;                                         \
            Bs[(lk+3)*132 + r] = vb.w;                                         \
        }                                                                      \
        __syncthreads();                                                       \
        _Pragma("unroll")                                                      \
        for (int kk = 0; kk < 16; ++kk) {                                      \
            float4 a0 = *(const float4*)(As + kk*132 + tm);                    \
            float4 a1 = *(const float4*)(As + kk*132 + tm + 4);                \
            float4 b0 = *(const float4*)(Bs + kk*132 + tn);                    \
            float4 b1 = *(const float4*)(Bs + kk*132 + tn + 4);                \
            float a[8] = {a0.x,a0.y,a0.z,a0.w,a1.x,a1.y,a1.z,a1.w};            \
            float b[8] = {b0.x,b0.y,b0.z,b0.w,b1.x,b1.y,b1.z,b1.w};            \
            _Pragma("unroll")                                                  \
            for (int i = 0; i < 8; i++)                                        \
                _Pragma("unroll")                                              \
                for (int j = 0; j < 8; j++) acc[i][j] = fmaf(a[i], b[j], acc[i][j]); \
        }                                                                      \
        __syncthreads();                                                       \
    }

// ---------------------------------------------------------------------------
// Kernel 1: QKV GEMM. grid (24, 32). Epilogue scatters to g_Q/g_K/g_V in
// (b,h,s,d) layout; Q pre-scaled by 0.125 = 64^-0.5.
// ---------------------------------------------------------------------------
__global__ void __launch_bounds__(256) qkv_gemm(const float* __restrict__ X,
                                                const float* __restrict__ W)
{
    GEMM_BODY(X, W)

    // n = h*192 + sel*64 + d ; 8 consecutive n share (h, sel) since 8 | 64
    const int n_base = n0 + tn;
    const int grp = n_base >> 6;          // 0..47
    const int h   = grp / 3;
    const int sel = grp - 3 * h;
    const int d0  = n_base & 63;
    float* dst = (sel == 0) ? g_Q : ((sel == 1) ? g_K : g_V);
    const float sc = (sel == 0) ? 0.125f : 1.0f;

#pragma unroll
    for (int i = 0; i < 8; i++) {
        int m = m0 + tm + i;
        int b = m >> 11;
        int s = m & 2047;
        size_t idx = (((size_t)(b * 16 + h)) * 2048 + s) * 64 + d0;
        float4 r0, r1;
        r0.x = acc[i][0]*sc; r0.y = acc[i][1]*sc; r0.z = acc[i][2]*sc; r0.w = acc[i][3]*sc;
        r1.x = acc[i][4]*sc; r1.y = acc[i][5]*sc; r1.z = acc[i][6]*sc; r1.w = acc[i][7]*sc;
        *(float4*)(dst + idx)     = r0;
        *(float4*)(dst + idx + 4) = r1;
    }
}

// ---------------------------------------------------------------------------
// Kernel 2: causal flash attention. grid (S/64 = 32, B*H = 32), 256 threads.
// Smem: Qt[d][r], Kt[d][c] (reused as P[r][c]), V[c][d] — 3*16KB = 48KB exactly.
// Thread (ty,tx) owns score/O microtile rows 4ty+i, cols 4tx+j.
// ---------------------------------------------------------------------------
__global__ void __launch_bounds__(256) flash_attn()
{
    __shared__ float Qt[64 * 64];
    __shared__ float Kt[64 * 64];   // reused as P after S is computed
    __shared__ float Vs[64 * 64];

    const int tid = threadIdx.x;
    const int qt_idx = blockIdx.x;
    const int bh = blockIdx.y;
    const int q0 = qt_idx * 64;

    const float* Qg = g_Q + (size_t)bh * S_ * 64;
    const float* Kg = g_K + (size_t)bh * S_ * 64;
    const float* Vg = g_V + (size_t)bh * S_ * 64;

    // transposed-load mapping (Q, K): 4 threads per row
    const int lr = tid >> 2;            // 0..63
    const int lc = (tid & 3) << 2;      // 0,4,8,12

    // Q tile -> Qt[d][r]
#pragma unroll
    for (int u = 0; u < 4; u++) {
        int d0 = lc + u * 16;
        float4 v = *(const float4*)(Qg + (size_t)(q0 + lr) * 64 + d0);
        Qt[(d0+0)*64 + lr] = v.x;
        Qt[(d0+1)*64 + lr] = v.y;
        Qt[(d0+2)*64 + lr] = v.z;
        Qt[(d0+3)*64 + lr] = v.w;
    }

    const int ty = tid >> 4;            // 0..15 -> rows 4ty..4ty+3
    const int tx = tid & 15;            // 0..15 -> cols 4tx..4tx+3
    const int vr = tid >> 4;            // V load: 16 rows/pass
    const int vd = (tid & 15) << 2;

    float m_r[4], l_r[4], o[4][4];
#pragma unroll
    for (int i = 0; i < 4; i++) {
        m_r[i] = -1e30f; l_r[i] = 0.f;
#pragma unroll
        for (int j = 0; j < 4; j++) o[i][j] = 0.f;
    }

    for (int t = 0; t <= qt_idx; t++) {
        __syncthreads();   // prev PV done (and Q stores visible on t=0)
        const int kv0 = t * 64;

        // K tile -> Kt[d][c]
#pragma unroll
        for (int u = 0; u < 4; u++) {
            int d0 = lc + u * 16;
            float4 v = *(const float4*)(Kg + (size_t)(kv0 + lr) * 64 + d0);
            Kt[(d0+0)*64 + lr] = v.x;
            Kt[(d0+1)*64 + lr] = v.y;
            Kt[(d0+2)*64 + lr] = v.z;
            Kt[(d0+3)*64 + lr] = v.w;
        }
        // V tile -> Vs[c][d] (natural, float4)
#pragma unroll
        for (int it = 0; it < 4; ++it) {
            int r = vr + it * 16;
            *(float4*)(Vs + r*64 + vd) = *(const float4*)(Vg + (size_t)(kv0 + r) * 64 + vd);
        }
        __syncthreads();

        // S = (Q*scale) @ K^T   (scale already folded into Q)
        float s[4][4];
#pragma unroll
        for (int i = 0; i < 4; i++)
#pragma unroll
            for (int j = 0; j < 4; j++) s[i][j] = 0.f;

#pragma unroll 4
        for (int d = 0; d < 64; d++) {
            float a0 = Qt[d*64 + 4*ty + 0];
            float a1 = Qt[d*64 + 4*ty + 1];
            float a2 = Qt[d*64 + 4*ty + 2];
            float a3 = Qt[d*64 + 4*ty + 3];
            float b0 = Kt[d*64 + 4*tx + 0];
            float b1 = Kt[d*64 + 4*tx + 1];
            float b2 = Kt[d*64 + 4*tx + 2];
            float b3 = Kt[d*64 + 4*tx + 3];
            s[0][0]=fmaf(a0,b0,s[0][0]); s[0][1]=fmaf(a0,b1,s[0][1]); s[0][2]=fmaf(a0,b2,s[0][2]); s[0][3]=fmaf(a0,b3,s[0][3]);
            s[1][0]=fmaf(a1,b0,s[1][0]); s[1][1]=fmaf(a1,b1,s[1][1]); s[1][2]=fmaf(a1,b2,s[1][2]); s[1][3]=fmaf(a1,b3,s[1][3]);
            s[2][0]=fmaf(a2,b0,s[2][0]); s[2][1]=fmaf(a2,b1,s[2][1]); s[2][2]=fmaf(a2,b2,s[2][2]); s[2][3]=fmaf(a2,b3,s[2][3]);
            s[3][0]=fmaf(a3,b0,s[3][0]); s[3][1]=fmaf(a3,b1,s[3][1]); s[3][2]=fmaf(a3,b2,s[3][2]); s[3][3]=fmaf(a3,b3,s[3][3]);
        }

        // causal mask (only diagonal tile)
        if (t == qt_idx) {
#pragma unroll
            for (int i = 0; i < 4; i++) {
                int qg = q0 + 4*ty + i;
#pragma unroll
                for (int j = 0; j < 4; j++) {
                    int kg = kv0 + 4*tx + j;
                    if (kg > qg) s[i][j] = -1e30f;
                }
            }
        }

        // online softmax (row reduce over the 16 tx lanes, width-16 shuffles)
#pragma unroll
        for (int i = 0; i < 4; i++) {
            float mn = fmaxf(fmaxf(s[i][0], s[i][1]), fmaxf(s[i][2], s[i][3]));
#pragma unroll
            for (int off = 8; off > 0; off >>= 1)
                mn = fmaxf(mn, __shfl_xor_sync(0xffffffffu, mn, off, 16));
            float mnew  = fmaxf(m_r[i], mn);
            float alpha = __expf(m_r[i] - mnew);
            m_r[i] = mnew;
            float ps = 0.f;
#pragma unroll
            for (int j = 0; j < 4; j++) {
                s[i][j] = __expf(s[i][j] - mnew);
                ps += s[i][j];
            }
#pragma unroll
            for (int off = 8; off > 0; off >>= 1)
                ps += __shfl_xor_sync(0xffffffffu, ps, off, 16);
            l_r[i] = l_r[i] * alpha + ps;
#pragma unroll
            for (int j = 0; j < 4; j++) o[i][j] *= alpha;
        }

        __syncthreads();   // everyone done reading Kt for S
        // P -> Kt buffer
#pragma unroll
        for (int i = 0; i < 4; i++)
#pragma unroll
            for (int j = 0; j < 4; j++)
                Kt[(4*ty + i)*64 + 4*tx + j] = s[i][j];
        __syncthreads();

        // O += P @ V
#pragma unroll 4
        for (int c = 0; c < 64; c++) {
            float p0 = Kt[(4*ty+0)*64 + c];
            float p1 = Kt[(4*ty+1)*64 + c];
            float p2 = Kt[(4*ty+2)*64 + c];
            float p3 = Kt[(4*ty+3)*64 + c];
            float v0 = Vs[c*64 + 4*tx + 0];
            float v1 = Vs[c*64 + 4*tx + 1];
            float v2 = Vs[c*64 + 4*tx + 2];
            float v3 = Vs[c*64 + 4*tx + 3];
            o[0][0]=fmaf(p0,v0,o[0][0]); o[0][1]=fmaf(p0,v1,o[0][1]); o[0][2]=fmaf(p0,v2,o[0][2]); o[0][3]=fmaf(p0,v3,o[0][3]);
            o[1][0]=fmaf(p1,v0,o[1][0]); o[1][1]=fmaf(p1,v1,o[1][1]); o[1][2]=fmaf(p1,v2,o[1][2]); o[1][3]=fmaf(p1,v3,o[1][3]);
            o[2][0]=fmaf(p2,v0,o[2][0]); o[2][1]=fmaf(p2,v1,o[2][1]); o[2][2]=fmaf(p2,v2,o[2][2]); o[2][3]=fmaf(p2,v3,o[2][3]);
            o[3][0]=fmaf(p3,v0,o[3][0]); o[3][1]=fmaf(p3,v1,o[3][1]); o[3][2]=fmaf(p3,v2,o[3][2]); o[3][3]=fmaf(p3,v3,o[3][3]);
        }
    }

    // write O in (b, s, h*64+d) layout
    const int b = bh >> 4;
    const int h = bh & 15;
#pragma unroll
    for (int i = 0; i < 4; i++) {
        float inv = 1.0f / l_r[i];
        float4 r;
        r.x = o[i][0]*inv; r.y = o[i][1]*inv; r.z = o[i][2]*inv; r.w = o[i][3]*inv;
        size_t q = (size_t)(q0 + 4*ty + i);
        *(float4*)(g_O + ((size_t)b * 2048 + q) * 1024 + h * 64 + tx * 4) = r;
    }
}

// ---------------------------------------------------------------------------
// Kernel 3: output projection. grid (8, 32). out = g_O @ w_proj^T + bias.
// ---------------------------------------------------------------------------
__global__ void __launch_bounds__(256) proj_gemm(const float* __restrict__ W,
                                                 const float* __restrict__ bias,
                                                 float* __restrict__ out)
{
    GEMM_BODY(g_O, W)

    const int n_base = n0 + tn;
    float4 bi0 = *(const float4*)(bias + n_base);
    float4 bi1 = *(const float4*)(bias + n_base + 4);

#pragma unroll
    for (int i = 0; i < 8; i++) {
        int m = m0 + tm + i;
        float4 r0, r1;
        r0.x = acc[i][0] + bi0.x; r0.y = acc[i][1] + bi0.y;
        r0.z = acc[i][2] + bi0.z; r0.w = acc[i][3] + bi0.w;
        r1.x = acc[i][4] + bi1.x; r1.y = acc[i][5] + bi1.y;
        r1.z = acc[i][6] + bi1.z; r1.w = acc[i][7] + bi1.w;
        *(float4*)(out + (size_t)m * 1024 + n_base)     = r0;
        *(float4*)(out + (size_t)m * 1024 + n_base + 4) = r1;
    }
}

// ---------------------------------------------------------------------------
extern "C" void kernel_launch(void* const* d_in, const int* in_sizes, int n_in,
                              void* d_out, int out_size)
{
    const float* x      = (const float*)d_in[0];  // (2,2048,1024)
    const float* w_qkv  = (const float*)d_in[1];  // (3072,1024)
    const float* w_proj = (const float*)d_in[2];  // (1024,1024)
    const float* b_proj = (const float*)d_in[3];  // (1024,)
    float* out = (float*)d_out;

    qkv_gemm<<<dim3(24, 32), 256>>>(x, w_qkv);
    flash_attn<<<dim3(32, 32), 256>>>();
    proj_gemm<<<dim3(8, 32), 256>>>(w_proj, b_proj, out);
}

// round 3
// speedup vs baseline: 1.3878x; 1.3878x over previous
#include <cuda_runtime.h>
#include <math.h>
#include <stdint.h>

#define B_  2
#define S_  2048
#define E_  1024
#define H_  16
#define HD_ 64

// Scratch (allocation-free: __device__ globals)
__device__ float g_Q[B_*H_*S_*HD_];   // (b,h,s,d), pre-scaled by hd^-0.5
__device__ float g_K[B_*H_*S_*HD_];   // (b,h,s,d)
__device__ float g_V[B_*H_*S_*HD_];   // (b,h,s,d)
__device__ float g_O[B_*S_*E_];       // (b,s,h*d) — attention out, proj input

// ============================================================================
// mma.sync tf32 helpers (PTX ISA sm_80+, no 'a'-suffix features needed)
// ============================================================================
__device__ __forceinline__ float tf32_rna(float x) {
    uint32_t r;
    asm("cvt.rna.tf32.f32 %0, %1;" : "=r"(r) : "f"(x));
    return __uint_as_float(r);
}

__device__ __forceinline__ void mma_tf32(float4& d,
                                         uint32_t a0, uint32_t a1, uint32_t a2, uint32_t a3,
                                         uint32_t b0, uint32_t b1)
{
    asm volatile(
        "mma.sync.aligned.m16n8k8.row.col.f32.tf32.tf32.f32 "
        "{%0,%1,%2,%3}, {%4,%5,%6,%7}, {%8,%9}, {%0,%1,%2,%3};"
        : "+f"(d.x), "+f"(d.y), "+f"(d.z), "+f"(d.w)
        : "r"(a0), "r"(a1), "r"(a2), "r"(a3), "r"(b0), "r"(b1));
}

// ============================================================================
// TF32 warp-MMA GEMM core: C[128x128] tile of A[M,1024] @ B[N,1024]^T.
// 256 threads = 8 warps (2x4), warp tile 64x32, m16n8k8 atoms, BK=16.
// Smem [row][k] stride 20 floats (fragment gather is bank-conflict-free).
// Double-buffered smem + register staging of the next global chunk.
// Result: acc[am][an] fragments; C row = wm+am*16+(lane/4)+{0,8},
//         C col = wn+an*8+(lane%4)*2+{0,1}.
// ============================================================================
#define KSTR 20

__device__ __forceinline__ void gemm_tf32_mma(const float* __restrict__ A,
                                              const float* __restrict__ Bm,
                                              int m0, int n0, float4 acc[4][4])
{
    __shared__ float As[2][128 * KSTR];
    __shared__ float Bs[2][128 * KSTR];

    const int tid  = threadIdx.x;
    const int lane = tid & 31;
    const int warp = tid >> 5;
    const int wm = (warp >> 2) * 64;   // 0 or 64
    const int wn = (warp & 3) * 32;    // 0..96
    const int g  = lane >> 2;          // 0..7
    const int t  = lane & 3;           // 0..3

    // staging-load mapping: 2 threads per row, 8 floats each
    const int row = tid >> 1;
    const int kc  = (tid & 1) * 8;
    const float* gA = A  + (size_t)(m0 + row) * 1024 + kc;
    const float* gB = Bm + (size_t)(n0 + row) * 1024 + kc;
    const int soff = row * KSTR + kc;

#pragma unroll
    for (int am = 0; am < 4; am++)
#pragma unroll
        for (int an = 0; an < 4; an++)
            acc[am][an] = make_float4(0.f, 0.f, 0.f, 0.f);

    // prologue: chunk 0 -> buffer 0
    {
        float4 va0 = *(const float4*)(gA);
        float4 va1 = *(const float4*)(gA + 4);
        float4 vb0 = *(const float4*)(gB);
        float4 vb1 = *(const float4*)(gB + 4);
        float4 ca0 = make_float4(tf32_rna(va0.x), tf32_rna(va0.y), tf32_rna(va0.z), tf32_rna(va0.w));
        float4 ca1 = make_float4(tf32_rna(va1.x), tf32_rna(va1.y), tf32_rna(va1.z), tf32_rna(va1.w));
        float4 cb0 = make_float4(tf32_rna(vb0.x), tf32_rna(vb0.y), tf32_rna(vb0.z), tf32_rna(vb0.w));
        float4 cb1 = make_float4(tf32_rna(vb1.x), tf32_rna(vb1.y), tf32_rna(vb1.z), tf32_rna(vb1.w));
        *(float4*)&As[0][soff]     = ca0;
        *(float4*)&As[0][soff + 4] = ca1;
        *(float4*)&Bs[0][soff]     = cb0;
        *(float4*)&Bs[0][soff + 4] = cb1;
    }
    __syncthreads();

    const int aOff = (wm + g) * KSTR + t;
    const int bOff = (wn + g) * KSTR + t;

    for (int c = 0; c < 64; ++c) {
        const int buf = c & 1;
        float4 va0, va1, vb0, vb1;
        if (c < 63) {
            va0 = *(const float4*)(gA + (c + 1) * 16);
            va1 = *(const float4*)(gA + (c + 1) * 16 + 4);
            vb0 = *(const float4*)(gB + (c + 1) * 16);
            vb1 = *(const float4*)(gB + (c + 1) * 16 + 4);
        }

        const float* as = As[buf];
        const float* bs = Bs[buf];
#pragma unroll
        for (int ks = 0; ks < 2; ++ks) {
            uint32_t af[4][4], bf[4][2];
#pragma unroll
            for (int am = 0; am < 4; am++) {
                const float* p = as + aOff + am * 16 * KSTR + ks * 8;
                af[am][0] = __float_as_uint(p[0]);
                af[am][1] = __float_as_uint(p[8 * KSTR]);
                af[am][2] = __float_as_uint(p[4]);
                af[am][3] = __float_as_uint(p[8 * KSTR + 4]);
            }
#pragma unroll
            for (int an = 0; an < 4; an++) {
                const float* p = bs + bOff + an * 8 * KSTR + ks * 8;
                bf[an][0] = __float_as_uint(p[0]);
                bf[an][1] = __float_as_uint(p[4]);
            }
#pragma unroll
            for (int am = 0; am < 4; am++)
#pragma unroll
                for (int an = 0; an < 4; an++)
                    mma_tf32(acc[am][an], af[am][0], af[am][1], af[am][2], af[am][3],
                             bf[an][0], bf[an][1]);
        }

        if (c < 63) {
            const int nb = (c + 1) & 1;
            float4 ca0 = make_float4(tf32_rna(va0.x), tf32_rna(va0.y), tf32_rna(va0.z), tf32_rna(va0.w));
            float4 ca1 = make_float4(tf32_rna(va1.x), tf32_rna(va1.y), tf32_rna(va1.z), tf32_rna(va1.w));
            float4 cb0 = make_float4(tf32_rna(vb0.x), tf32_rna(vb0.y), tf32_rna(vb0.z), tf32_rna(vb0.w));
            float4 cb1 = make_float4(tf32_rna(vb1.x), tf32_rna(vb1.y), tf32_rna(vb1.z), tf32_rna(vb1.w));
            *(float4*)&As[nb][soff]     = ca0;
            *(float4*)&As[nb][soff + 4] = ca1;
            *(float4*)&Bs[nb][soff]     = cb0;
            *(float4*)&Bs[nb][soff + 4] = cb1;
        }
        __syncthreads();
    }
}

// ---------------------------------------------------------------------------
// Kernel 1: QKV GEMM (tf32 mma.sync). grid (24, 32) x 256 thr.
// Epilogue scatters to g_Q/g_K/g_V in (b,h,s,d); Q pre-scaled by 0.125.
// ---------------------------------------------------------------------------
__global__ void __launch_bounds__(256) qkv_mma(const float* __restrict__ X,
                                               const float* __restrict__ W)
{
    const int m0 = blockIdx.y * 128;
    const int n0 = blockIdx.x * 128;
    float4 acc[4][4];
    gemm_tf32_mma(X, W, m0, n0, acc);

    const int lane = threadIdx.x & 31;
    const int warp = threadIdx.x >> 5;
    const int wm = (warp >> 2) * 64;
    const int wn = (warp & 3) * 32;
    const int g  = lane >> 2;
    const int t  = lane & 3;

#pragma unroll
    for (int an = 0; an < 4; an++) {
        const int ng  = n0 + wn + an * 8;        // n = h*192 + sel*64 + d
        const int grp = ng >> 6;
        const int h   = grp / 3;
        const int sel = grp - 3 * h;
        const int db  = (ng & 63) + t * 2;
        float* dst = (sel == 0) ? g_Q : ((sel == 1) ? g_K : g_V);
        const float sc = (sel == 0) ? 0.125f : 1.0f;
#pragma unroll
        for (int am = 0; am < 4; am++) {
#pragma unroll
            for (int half = 0; half < 2; half++) {
                const int m = m0 + wm + am * 16 + g + half * 8;
                const int b = m >> 11;
                const int s = m & 2047;
                float2 v;
                v.x = (half ? acc[am][an].z : acc[am][an].x) * sc;
                v.y = (half ? acc[am][an].w : acc[am][an].y) * sc;
                *(float2*)(dst + (((size_t)(b * 16 + h)) * 2048 + s) * 64 + db) = v;
            }
        }
    }
}

// ---------------------------------------------------------------------------
// Kernel 3: output projection (tf32 mma.sync). grid (8, 32) x 256 thr.
// ---------------------------------------------------------------------------
__global__ void __launch_bounds__(256) proj_mma(const float* __restrict__ W,
                                                const float* __restrict__ bias,
                                                float* __restrict__ out)
{
    const int m0 = blockIdx.y * 128;
    const int n0 = blockIdx.x * 128;
    float4 acc[4][4];
    gemm_tf32_mma(g_O, W, m0, n0, acc);

    const int lane = threadIdx.x & 31;
    const int warp = threadIdx.x >> 5;
    const int wm = (warp >> 2) * 64;
    const int wn = (warp & 3) * 32;
    const int g  = lane >> 2;
    const int t  = lane & 3;

#pragma unroll
    for (int an = 0; an < 4; an++) {
        const int ng = n0 + wn + an * 8 + t * 2;
        const float2 bi = *(const float2*)(bias + ng);
#pragma unroll
        for (int am = 0; am < 4; am++) {
#pragma unroll
            for (int half = 0; half < 2; half++) {
                const int m = m0 + wm + am * 16 + g + half * 8;
                float2 v;
                v.x = (half ? acc[am][an].z : acc[am][an].x) + bi.x;
                v.y = (half ? acc[am][an].w : acc[am][an].y) + bi.y;
                *(float2*)(out + (size_t)m * 1024 + ng) = v;
            }
        }
    }
}

// ---------------------------------------------------------------------------
// Kernel 2: causal flash attention (fp32 SIMT, unchanged — round-1 verified).
// grid (S/64 = 32, B*H = 32), 256 threads. 48KB static smem.
// ---------------------------------------------------------------------------
__global__ void __launch_bounds__(256) flash_attn()
{
    __shared__ float Qt[64 * 64];
    __shared__ float Kt[64 * 64];   // reused as P after S is computed
    __shared__ float Vs[64 * 64];

    const int tid = threadIdx.x;
    const int qt_idx = blockIdx.x;
    const int bh = blockIdx.y;
    const int q0 = qt_idx * 64;

    const float* Qg = g_Q + (size_t)bh * S_ * 64;
    const float* Kg = g_K + (size_t)bh * S_ * 64;
    const float* Vg = g_V + (size_t)bh * S_ * 64;

    const int lr = tid >> 2;            // 0..63
    const int lc = (tid & 3) << 2;      // 0,4,8,12

#pragma unroll
    for (int u = 0; u < 4; u++) {
        int d0 = lc + u * 16;
        float4 v = *(const float4*)(Qg + (size_t)(q0 + lr) * 64 + d0);
        Qt[(d0+0)*64 + lr] = v.x;
        Qt[(d0+1)*64 + lr] = v.y;
        Qt[(d0+2)*64 + lr] = v.z;
        Qt[(d0+3)*64 + lr] = v.w;
    }

    const int ty = tid >> 4;
    const int tx = tid & 15;
    const int vr = tid >> 4;
    const int vd = (tid & 15) << 2;

    float m_r[4], l_r[4], o[4][4];
#pragma unroll
    for (int i = 0; i < 4; i++) {
        m_r[i] = -1e30f; l_r[i] = 0.f;
#pragma unroll
        for (int j = 0; j < 4; j++) o[i][j] = 0.f;
    }

    for (int t = 0; t <= qt_idx; t++) {
        __syncthreads();
        const int kv0 = t * 64;

#pragma unroll
        for (int u = 0; u < 4; u++) {
            int d0 = lc + u * 16;
            float4 v = *(const float4*)(Kg + (size_t)(kv0 + lr) * 64 + d0);
            Kt[(d0+0)*64 + lr] = v.x;
            Kt[(d0+1)*64 + lr] = v.y;
            Kt[(d0+2)*64 + lr] = v.z;
            Kt[(d0+3)*64 + lr] = v.w;
        }
#pragma unroll
        for (int it = 0; it < 4; ++it) {
            int r = vr + it * 16;
            *(float4*)(Vs + r*64 + vd) = *(const float4*)(Vg + (size_t)(kv0 + r) * 64 + vd);
        }
        __syncthreads();

        float s[4][4];
#pragma unroll
        for (int i = 0; i < 4; i++)
#pragma unroll
            for (int j = 0; j < 4; j++) s[i][j] = 0.f;

#pragma unroll 4
        for (int d = 0; d < 64; d++) {
            float a0 = Qt[d*64 + 4*ty + 0];
            float a1 = Qt[d*64 + 4*ty + 1];
            float a2 = Qt[d*64 + 4*ty + 2];
            float a3 = Qt[d*64 + 4*ty + 3];
            float b0 = Kt[d*64 + 4*tx + 0];
            float b1 = Kt[d*64 + 4*tx + 1];
            float b2 = Kt[d*64 + 4*tx + 2];
            float b3 = Kt[d*64 + 4*tx + 3];
            s[0][0]=fmaf(a0,b0,s[0][0]); s[0][1]=fmaf(a0,b1,s[0][1]); s[0][2]=fmaf(a0,b2,s[0][2]); s[0][3]=fmaf(a0,b3,s[0][3]);
            s[1][0]=fmaf(a1,b0,s[1][0]); s[1][1]=fmaf(a1,b1,s[1][1]); s[1][2]=fmaf(a1,b2,s[1][2]); s[1][3]=fmaf(a1,b3,s[1][3]);
            s[2][0]=fmaf(a2,b0,s[2][0]); s[2][1]=fmaf(a2,b1,s[2][1]); s[2][2]=fmaf(a2,b2,s[2][2]); s[2][3]=fmaf(a2,b3,s[2][3]);
            s[3][0]=fmaf(a3,b0,s[3][0]); s[3][1]=fmaf(a3,b1,s[3][1]); s[3][2]=fmaf(a3,b2,s[3][2]); s[3][3]=fmaf(a3,b3,s[3][3]);
        }

        if (t == qt_idx) {
#pragma unroll
            for (int i = 0; i < 4; i++) {
                int qg = q0 + 4*ty + i;
#pragma unroll
                for (int j = 0; j < 4; j++) {
                    int kg = kv0 + 4*tx + j;
                    if (kg > qg) s[i][j] = -1e30f;
                }
            }
        }

#pragma unroll
        for (int i = 0; i < 4; i++) {
            float mn = fmaxf(fmaxf(s[i][0], s[i][1]), fmaxf(s[i][2], s[i][3]));
#pragma unroll
            for (int off = 8; off > 0; off >>= 1)
                mn = fmaxf(mn, __shfl_xor_sync(0xffffffffu, mn, off, 16));
            float mnew  = fmaxf(m_r[i], mn);
            float alpha = __expf(m_r[i] - mnew);
            m_r[i] = mnew;
            float ps = 0.f;
#pragma unroll
            for (int j = 0; j < 4; j++) {
                s[i][j] = __expf(s[i][j] - mnew);
                ps += s[i][j];
            }
#pragma unroll
            for (int off = 8; off > 0; off >>= 1)
                ps += __shfl_xor_sync(0xffffffffu, ps, off, 16);
            l_r[i] = l_r[i] * alpha + ps;
#pragma unroll
            for (int j = 0; j < 4; j++) o[i][j] *= alpha;
        }

        __syncthreads();
#pragma unroll
        for (int i = 0; i < 4; i++)
#pragma unroll
            for (int j = 0; j < 4; j++)
                Kt[(4*ty + i)*64 + 4*tx + j] = s[i][j];
        __syncthreads();

#pragma unroll 4
        for (int c = 0; c < 64; c++) {
            float p0 = Kt[(4*ty+0)*64 + c];
            float p1 = Kt[(4*ty+1)*64 + c];
            float p2 = Kt[(4*ty+2)*64 + c];
            float p3 = Kt[(4*ty+3)*64 + c];
            float v0 = Vs[c*64 + 4*tx + 0];
            float v1 = Vs[c*64 + 4*tx + 1];
            float v2 = Vs[c*64 + 4*tx + 2];
            float v3 = Vs[c*64 + 4*tx + 3];
            o[0][0]=fmaf(p0,v0,o[0][0]); o[0][1]=fmaf(p0,v1,o[0][1]); o[0][2]=fmaf(p0,v2,o[0][2]); o[0][3]=fmaf(p0,v3,o[0][3]);
            o[1][0]=fmaf(p1,v0,o[1][0]); o[1][1]=fmaf(p1,v1,o[1][1]); o[1][2]=fmaf(p1,v2,o[1][2]); o[1][3]=fmaf(p1,v3,o[1][3]);
            o[2][0]=fmaf(p2,v0,o[2][0]); o[2][1]=fmaf(p2,v1,o[2][1]); o[2][2]=fmaf(p2,v2,o[2][2]); o[2][3]=fmaf(p2,v3,o[2][3]);
            o[3][0]=fmaf(p3,v0,o[3][0]); o[3][1]=fmaf(p3,v1,o[3][1]); o[3][2]=fmaf(p3,v2,o[3][2]); o[3][3]=fmaf(p3,v3,o[3][3]);
        }
    }

    const int b = bh >> 4;
    const int h = bh & 15;
#pragma unroll
    for (int i = 0; i < 4; i++) {
        float inv = 1.0f / l_r[i];
        float4 r;
        r.x = o[i][0]*inv; r.y = o[i][1]*inv; r.z = o[i][2]*inv; r.w = o[i][3]*inv;
        size_t q = (size_t)(q0 + 4*ty + i);
        *(float4*)(g_O + ((size_t)b * 2048 + q) * 1024 + h * 64 + tx * 4) = r;
    }
}

// ---------------------------------------------------------------------------
extern "C" void kernel_launch(void* const* d_in, const int* in_sizes, int n_in,
                              void* d_out, int out_size)
{
    const float* x      = (const float*)d_in[0];  // (2,2048,1024)
    const float* w_qkv  = (const float*)d_in[1];  // (3072,1024)
    const float* w_proj = (const float*)d_in[2];  // (1024,1024)
    const float* b_proj = (const float*)d_in[3];  // (1024,)
    float* out = (float*)d_out;

    qkv_mma<<<dim3(24, 32), 256>>>(x, w_qkv);
    flash_attn<<<dim3(32, 32), 256>>>();
    proj_mma<<<dim3(8, 32), 256>>>(w_proj, b_proj, out);
}

// round 4
// speedup vs baseline: 2.2585x; 1.6274x over previous
#include <cuda_runtime.h>
#include <math.h>
#include <stdint.h>

#define B_  2
#define S_  2048
#define E_  1024
#define H_  16
#define HD_ 64

// Scratch (allocation-free: __device__ globals)
// g_Q: tf32-rounded, pre-scaled by 0.125*log2(e)  (scores come out in base-2)
// g_K, g_V: tf32-rounded (rna) so attention MMAs see rna instead of rz inputs
__device__ float g_Q[B_*H_*S_*HD_];
__device__ float g_K[B_*H_*S_*HD_];
__device__ float g_V[B_*H_*S_*HD_];
__device__ float g_O[B_*S_*E_];       // (b,s,h*d) — attention out, proj input

// ============================================================================
// PTX helpers (plain sm_80+ ISA — no 'a'-suffix features)
// ============================================================================
__device__ __forceinline__ float tf32_rna(float x) {
    uint32_t r;
    asm("cvt.rna.tf32.f32 %0, %1;" : "=r"(r) : "f"(x));
    return __uint_as_float(r);
}

__device__ __forceinline__ void mma_tf32(float4& d,
                                         uint32_t a0, uint32_t a1, uint32_t a2, uint32_t a3,
                                         uint32_t b0, uint32_t b1)
{
    asm volatile(
        "mma.sync.aligned.m16n8k8.row.col.f32.tf32.tf32.f32 "
        "{%0,%1,%2,%3}, {%4,%5,%6,%7}, {%8,%9}, {%0,%1,%2,%3};"
        : "+f"(d.x), "+f"(d.y), "+f"(d.z), "+f"(d.w)
        : "r"(a0), "r"(a1), "r"(a2), "r"(a3), "r"(b0), "r"(b1));
}

__device__ __forceinline__ uint32_t smem_u32(const void* p) {
    uint32_t a;
    asm("{ .reg .u64 tmp; cvta.to.shared.u64 tmp, %1; cvt.u32.u64 %0, tmp; }"
        : "=r"(a) : "l"(p));
    return a;
}

__device__ __forceinline__ void cp16(uint32_t dst, const void* src) {
    asm volatile("cp.async.cg.shared.global [%0], [%1], 16;"
                 :: "r"(dst), "l"(src) : "memory");
}
#define CP_COMMIT() asm volatile("cp.async.commit_group;" ::: "memory")
#define CP_WAIT0()  asm volatile("cp.async.wait_group 0;" ::: "memory")

// exp2 on the FMA pipe: degree-6 Taylor on f in [-0.5, 0.5], rel err ~1.2e-7.
// Valid for x <= 0 (clamped at -126 -> result ~0).
__device__ __forceinline__ float exp2p(float x) {
    x = fmaxf(x, -126.0f);
    float n = rintf(x);
    float f = x - n;
    float p = 1.5403530e-4f;
    p = fmaf(p, f, 1.3333558e-3f);
    p = fmaf(p, f, 9.6181291e-3f);
    p = fmaf(p, f, 5.5504109e-2f);
    p = fmaf(p, f, 2.4022651e-1f);
    p = fmaf(p, f, 6.9314718e-1f);
    p = fmaf(p, f, 1.0f);
    float s = __int_as_float(((int)n + 127) << 23);
    return p * s;
}

// ============================================================================
// TF32 warp-MMA GEMM core (round-3 verified): C[128x128] of A[M,1024]@B[N,1024]^T
// ============================================================================
#define KSTR 20

__device__ __forceinline__ void gemm_tf32_mma(const float* __restrict__ A,
                                              const float* __restrict__ Bm,
                                              int m0, int n0, float4 acc[4][4])
{
    __shared__ float As[2][128 * KSTR];
    __shared__ float Bs[2][128 * KSTR];

    const int tid  = threadIdx.x;
    const int lane = tid & 31;
    const int warp = tid >> 5;
    const int wm = (warp >> 2) * 64;
    const int wn = (warp & 3) * 32;
    const int g  = lane >> 2;
    const int t  = lane & 3;

    const int row = tid >> 1;
    const int kc  = (tid & 1) * 8;
    const float* gA = A  + (size_t)(m0 + row) * 1024 + kc;
    const float* gB = Bm + (size_t)(n0 + row) * 1024 + kc;
    const int soff = row * KSTR + kc;

#pragma unroll
    for (int am = 0; am < 4; am++)
#pragma unroll
        for (int an = 0; an < 4; an++)
            acc[am][an] = make_float4(0.f, 0.f, 0.f, 0.f);

    {
        float4 va0 = *(const float4*)(gA);
        float4 va1 = *(const float4*)(gA + 4);
        float4 vb0 = *(const float4*)(gB);
        float4 vb1 = *(const float4*)(gB + 4);
        float4 ca0 = make_float4(tf32_rna(va0.x), tf32_rna(va0.y), tf32_rna(va0.z), tf32_rna(va0.w));
        float4 ca1 = make_float4(tf32_rna(va1.x), tf32_rna(va1.y), tf32_rna(va1.z), tf32_rna(va1.w));
        float4 cb0 = make_float4(tf32_rna(vb0.x), tf32_rna(vb0.y), tf32_rna(vb0.z), tf32_rna(vb0.w));
        float4 cb1 = make_float4(tf32_rna(vb1.x), tf32_rna(vb1.y), tf32_rna(vb1.z), tf32_rna(vb1.w));
        *(float4*)&As[0][soff]     = ca0;
        *(float4*)&As[0][soff + 4] = ca1;
        *(float4*)&Bs[0][soff]     = cb0;
        *(float4*)&Bs[0][soff + 4] = cb1;
    }
    __syncthreads();

    const int aOff = (wm + g) * KSTR + t;
    const int bOff = (wn + g) * KSTR + t;

    for (int c = 0; c < 64; ++c) {
        const int buf = c & 1;
        float4 va0, va1, vb0, vb1;
        if (c < 63) {
            va0 = *(const float4*)(gA + (c + 1) * 16);
            va1 = *(const float4*)(gA + (c + 1) * 16 + 4);
            vb0 = *(const float4*)(gB + (c + 1) * 16);
            vb1 = *(const float4*)(gB + (c + 1) * 16 + 4);
        }

        const float* as = As[buf];
        const float* bs = Bs[buf];
#pragma unroll
        for (int ks = 0; ks < 2; ++ks) {
            uint32_t af[4][4], bf[4][2];
#pragma unroll
            for (int am = 0; am < 4; am++) {
                const float* p = as + aOff + am * 16 * KSTR + ks * 8;
                af[am][0] = __float_as_uint(p[0]);
                af[am][1] = __float_as_uint(p[8 * KSTR]);
                af[am][2] = __float_as_uint(p[4]);
                af[am][3] = __float_as_uint(p[8 * KSTR + 4]);
            }
#pragma unroll
            for (int an = 0; an < 4; an++) {
                const float* p = bs + bOff + an * 8 * KSTR + ks * 8;
                bf[an][0] = __float_as_uint(p[0]);
                bf[an][1] = __float_as_uint(p[4]);
            }
#pragma unroll
            for (int am = 0; am < 4; am++)
#pragma unroll
                for (int an = 0; an < 4; an++)
                    mma_tf32(acc[am][an], af[am][0], af[am][1], af[am][2], af[am][3],
                             bf[an][0], bf[an][1]);
        }

        if (c < 63) {
            const int nb = (c + 1) & 1;
            float4 ca0 = make_float4(tf32_rna(va0.x), tf32_rna(va0.y), tf32_rna(va0.z), tf32_rna(va0.w));
            float4 ca1 = make_float4(tf32_rna(va1.x), tf32_rna(va1.y), tf32_rna(va1.z), tf32_rna(va1.w));
            float4 cb0 = make_float4(tf32_rna(vb0.x), tf32_rna(vb0.y), tf32_rna(vb0.z), tf32_rna(vb0.w));
            float4 cb1 = make_float4(tf32_rna(vb1.x), tf32_rna(vb1.y), tf32_rna(vb1.z), tf32_rna(vb1.w));
            *(float4*)&As[nb][soff]     = ca0;
            *(float4*)&As[nb][soff + 4] = ca1;
            *(float4*)&Bs[nb][soff]     = cb0;
            *(float4*)&Bs[nb][soff + 4] = cb1;
        }
        __syncthreads();
    }
}

// ---------------------------------------------------------------------------
// Kernel 1: QKV GEMM. Epilogue scatters tf32-rounded Q/K/V; Q scaled by
// 0.125*log2(e) so attention scores are directly in base-2 units.
// ---------------------------------------------------------------------------
#define QSCALE 0.18033688011112042f   // 0.125 * log2(e)

__global__ void __launch_bounds__(256) qkv_mma(const float* __restrict__ X,
                                               const float* __restrict__ W)
{
    const int m0 = blockIdx.y * 128;
    const int n0 = blockIdx.x * 128;
    float4 acc[4][4];
    gemm_tf32_mma(X, W, m0, n0, acc);

    const int lane = threadIdx.x & 31;
    const int warp = threadIdx.x >> 5;
    const int wm = (warp >> 2) * 64;
    const int wn = (warp & 3) * 32;
    const int g  = lane >> 2;
    const int t  = lane & 3;

#pragma unroll
    for (int an = 0; an < 4; an++) {
        const int ng  = n0 + wn + an * 8;        // n = h*192 + sel*64 + d
        const int grp = ng >> 6;
        const int h   = grp / 3;
        const int sel = grp - 3 * h;
        const int db  = (ng & 63) + t * 2;
        float* dst = (sel == 0) ? g_Q : ((sel == 1) ? g_K : g_V);
        const float sc = (sel == 0) ? QSCALE : 1.0f;
#pragma unroll
        for (int am = 0; am < 4; am++) {
#pragma unroll
            for (int half = 0; half < 2; half++) {
                const int m = m0 + wm + am * 16 + g + half * 8;
                const int b = m >> 11;
                const int s = m & 2047;
                float2 v;
                v.x = tf32_rna((half ? acc[am][an].z : acc[am][an].x) * sc);
                v.y = tf32_rna((half ? acc[am][an].w : acc[am][an].y) * sc);
                *(float2*)(dst + (((size_t)(b * 16 + h)) * 2048 + s) * 64 + db) = v;
            }
        }
    }
}

// ---------------------------------------------------------------------------
// Kernel 3: output projection (unchanged).
// ---------------------------------------------------------------------------
__global__ void __launch_bounds__(256) proj_mma(const float* __restrict__ W,
                                                const float* __restrict__ bias,
                                                float* __restrict__ out)
{
    const int m0 = blockIdx.y * 128;
    const int n0 = blockIdx.x * 128;
    float4 acc[4][4];
    gemm_tf32_mma(g_O, W, m0, n0, acc);

    const int lane = threadIdx.x & 31;
    const int warp = threadIdx.x >> 5;
    const int wm = (warp >> 2) * 64;
    const int wn = (warp & 3) * 32;
    const int g  = lane >> 2;
    const int t  = lane & 3;

#pragma unroll
    for (int an = 0; an < 4; an++) {
        const int ng = n0 + wn + an * 8 + t * 2;
        const float2 bi = *(const float2*)(bias + ng);
#pragma unroll
        for (int am = 0; am < 4; am++) {
#pragma unroll
            for (int half = 0; half < 2; half++) {
                const int m = m0 + wm + am * 16 + g + half * 8;
                float2 v;
                v.x = (half ? acc[am][an].z : acc[am][an].x) + bi.x;
                v.y = (half ? acc[am][an].w : acc[am][an].y) + bi.y;
                *(float2*)(out + (size_t)m * 1024 + ng) = v;
            }
        }
    }
}

// ============================================================================
// Kernel 2: tensor-core causal flash attention.
// CTA: 128 q-rows x 64 kv-tile, 8 warps (each 16 rows), m16n8k8 tf32 MMAs.
// cp.async double-buffered K/V; P via padded smem; exp2 by FMA polynomial.
// Grid (16, 32); heavy q-tiles scheduled first (qt = 15 - bx).
// Smem (floats): K[2][64][68] | V[2][64][72] | P/Q[128][68]
// ============================================================================
#define KSTRD 68
#define VSTRD 72
#define KBUF  (64*KSTRD)             // 4352
#define OFF_V (2*KBUF)               // 8704
#define VBUF  (64*VSTRD)             // 4608
#define OFF_P (OFF_V + 2*VBUF)       // 17920
#define FA_SMEM_BYTES ((OFF_P + 128*KSTRD) * 4)   // 106496

__global__ void __launch_bounds__(256, 1) flash_attn_tc()
{
    extern __shared__ float sm[];
    const uint32_t smu = smem_u32(sm);
    const int tid  = threadIdx.x;
    const int lane = tid & 31;
    const int warp = tid >> 5;
    const int g  = lane >> 2;
    const int t4 = lane & 3;
    const int qt = 15 - (int)blockIdx.x;
    const int bh = blockIdx.y;
    const int q0 = qt * 128;
    const int wr = warp * 16;
    const int tmax = 2 * qt + 1;

    const float* Qg = g_Q + (size_t)bh * S_ * 64;
    const float* Kg = g_K + (size_t)bh * S_ * 64;
    const float* Vg = g_V + (size_t)bh * S_ * 64;

    // kick off K/V tile 0 async loads first (overlaps with Q staging)
    {
        const int r = tid >> 2;
        const int c = (tid & 3) * 16;
        const float* ks = Kg + (size_t)r * 64 + c;
        const float* vs = Vg + (size_t)r * 64 + c;
        const uint32_t kd = smu + (uint32_t)(r * KSTRD + c) * 4;
        const uint32_t vd = smu + (uint32_t)(OFF_V + r * VSTRD + c) * 4;
#pragma unroll
        for (int j = 0; j < 4; j++) {
            cp16(kd + j * 16, ks + j * 4);
            cp16(vd + j * 16, vs + j * 4);
        }
        CP_COMMIT();
    }

    // stage Q tile into P region (coalesced), then pull warp fragments
    {
        const int r  = tid >> 1;
        const int c0 = (tid & 1) * 32;
        const float* src = Qg + (size_t)(q0 + r) * 64 + c0;
        float* dst = sm + OFF_P + r * KSTRD + c0;
#pragma unroll
        for (int j = 0; j < 8; j++)
            *(float4*)(dst + j * 4) = *(const float4*)(src + j * 4);
    }
    __syncthreads();

    uint32_t qf[8][4];
#pragma unroll
    for (int kk = 0; kk < 8; kk++) {
        const float* p = sm + OFF_P + (wr + g) * KSTRD + kk * 8 + t4;
        qf[kk][0] = __float_as_uint(p[0]);
        qf[kk][1] = __float_as_uint(p[8 * KSTRD]);
        qf[kk][2] = __float_as_uint(p[4]);
        qf[kk][3] = __float_as_uint(p[8 * KSTRD + 4]);
    }

    float m2[2] = {-1e30f, -1e30f};
    float l2[2] = {0.f, 0.f};
    float4 of[8];
#pragma unroll
    for (int an = 0; an < 8; an++) of[an] = make_float4(0.f, 0.f, 0.f, 0.f);

    for (int t = 0; t <= tmax; t++) {
        CP_WAIT0();
        __syncthreads();   // tile t resident; also fences Q-frag reads vs P writes

        if (t < tmax) {    // prefetch tile t+1 into the other buffer
            const int kv1 = (t + 1) * 64;
            const int buf = (t + 1) & 1;
            const int r = tid >> 2;
            const int c = (tid & 3) * 16;
            const float* ks = Kg + (size_t)(kv1 + r) * 64 + c;
            const float* vs = Vg + (size_t)(kv1 + r) * 64 + c;
            const uint32_t kd = smu + (uint32_t)(buf * KBUF + r * KSTRD + c) * 4;
            const uint32_t vd = smu + (uint32_t)(OFF_V + buf * VBUF + r * VSTRD + c) * 4;
#pragma unroll
            for (int j = 0; j < 4; j++) {
                cp16(kd + j * 16, ks + j * 4);
                cp16(vd + j * 16, vs + j * 4);
            }
            CP_COMMIT();
        }

        const int kv0 = t * 64;
        if (kv0 <= q0 + wr + 15) {   // warp has at least one unmasked row
            const float* smK = sm + (t & 1) * KBUF;
            const float* smV = sm + OFF_V + (t & 1) * VBUF;

            // S = Q @ K^T  (base-2 scaled already)
            float4 sf[8];
#pragma unroll
            for (int an = 0; an < 8; an++) sf[an] = make_float4(0.f, 0.f, 0.f, 0.f);
#pragma unroll
            for (int kk = 0; kk < 8; kk++) {
#pragma unroll
                for (int an = 0; an < 8; an++) {
                    const float* bp = smK + (an * 8 + g) * KSTRD + kk * 8 + t4;
                    mma_tf32(sf[an], qf[kk][0], qf[kk][1], qf[kk][2], qf[kk][3],
                             __float_as_uint(bp[0]), __float_as_uint(bp[4]));
                }
            }

            // causal mask (only near-diagonal tiles)
            if (kv0 + 63 > q0 + wr) {
                const int r0 = q0 + wr + g;
                const int r1 = r0 + 8;
#pragma unroll
                for (int an = 0; an < 8; an++) {
                    const int col = kv0 + an * 8 + 2 * t4;
                    if (col     > r0) sf[an].x = -1e30f;
                    if (col + 1 > r0) sf[an].y = -1e30f;
                    if (col     > r1) sf[an].z = -1e30f;
                    if (col + 1 > r1) sf[an].w = -1e30f;
                }
            }

            // online softmax (base-2, polynomial exp2 on FMA pipe)
            float mt0 = -1e30f, mt1 = -1e30f;
#pragma unroll
            for (int an = 0; an < 8; an++) {
                mt0 = fmaxf(mt0, fmaxf(sf[an].x, sf[an].y));
                mt1 = fmaxf(mt1, fmaxf(sf[an].z, sf[an].w));
            }
            mt0 = fmaxf(mt0, __shfl_xor_sync(0xffffffffu, mt0, 1));
            mt0 = fmaxf(mt0, __shfl_xor_sync(0xffffffffu, mt0, 2));
            mt1 = fmaxf(mt1, __shfl_xor_sync(0xffffffffu, mt1, 1));
            mt1 = fmaxf(mt1, __shfl_xor_sync(0xffffffffu, mt1, 2));

            const float mn0 = fmaxf(m2[0], mt0);
            const float mn1 = fmaxf(m2[1], mt1);
            const float a0 = exp2p(m2[0] - mn0);
            const float a1 = exp2p(m2[1] - mn1);
            m2[0] = mn0; m2[1] = mn1;

            float s0 = 0.f, s1 = 0.f;
#pragma unroll
            for (int an = 0; an < 8; an++) {
                sf[an].x = tf32_rna(exp2p(sf[an].x - mn0));
                sf[an].y = tf32_rna(exp2p(sf[an].y - mn0));
                sf[an].z = tf32_rna(exp2p(sf[an].z - mn1));
                sf[an].w = tf32_rna(exp2p(sf[an].w - mn1));
                s0 += sf[an].x + sf[an].y;
                s1 += sf[an].z + sf[an].w;
            }
            s0 += __shfl_xor_sync(0xffffffffu, s0, 1);
            s0 += __shfl_xor_sync(0xffffffffu, s0, 2);
            s1 += __shfl_xor_sync(0xffffffffu, s1, 1);
            s1 += __shfl_xor_sync(0xffffffffu, s1, 2);
            l2[0] = l2[0] * a0 + s0;
            l2[1] = l2[1] * a1 + s1;

#pragma unroll
            for (int an = 0; an < 8; an++) {
                of[an].x *= a0; of[an].y *= a0;
                of[an].z *= a1; of[an].w *= a1;
            }

            // P -> smem (own rows only)
            {
                float* pp = sm + OFF_P + (wr + g) * KSTRD;
#pragma unroll
                for (int an = 0; an < 8; an++) {
                    *(float2*)(pp + an * 8 + 2 * t4) = make_float2(sf[an].x, sf[an].y);
                    *(float2*)(pp + 8 * KSTRD + an * 8 + 2 * t4) = make_float2(sf[an].z, sf[an].w);
                }
            }
            __syncwarp();

            // O += P @ V
#pragma unroll
            for (int kk = 0; kk < 8; kk++) {
                const float* ap = sm + OFF_P + (wr + g) * KSTRD + kk * 8 + t4;
                const uint32_t A0 = __float_as_uint(ap[0]);
                const uint32_t A1 = __float_as_uint(ap[8 * KSTRD]);
                const uint32_t A2 = __float_as_uint(ap[4]);
                const uint32_t A3 = __float_as_uint(ap[8 * KSTRD + 4]);
#pragma unroll
                for (int an = 0; an < 8; an++) {
                    const float* vp = smV + (kk * 8 + t4) * VSTRD + an * 8 + g;
                    mma_tf32(of[an], A0, A1, A2, A3,
                             __float_as_uint(vp[0]), __float_as_uint(vp[4 * VSTRD]));
                }
            }
        }
        __syncthreads();   // all warps done with this tile's K/V and their P rows
    }

    // epilogue: normalize and write (b, s, h*64+d)
    const int b = bh >> 4;
    const int h = bh & 15;
    const float i0 = 1.0f / l2[0];
    const float i1 = 1.0f / l2[1];
    const int r0 = q0 + wr + g;
    const int r1 = r0 + 8;
    float* o0 = g_O + ((size_t)b * 2048 + r0) * 1024 + h * 64;
    float* o1 = g_O + ((size_t)b * 2048 + r1) * 1024 + h * 64;
#pragma unroll
    for (int an = 0; an < 8; an++) {
        const int d = an * 8 + 2 * t4;
        *(float2*)(o0 + d) = make_float2(of[an].x * i0, of[an].y * i0);
        *(float2*)(o1 + d) = make_float2(of[an].z * i1, of[an].w * i1);
    }
}

// ---------------------------------------------------------------------------
extern "C" void kernel_launch(void* const* d_in, const int* in_sizes, int n_in,
                              void* d_out, int out_size)
{
    const float* x      = (const float*)d_in[0];  // (2,2048,1024)
    const float* w_qkv  = (const float*)d_in[1];  // (3072,1024)
    const float* w_proj = (const float*)d_in[2];  // (1024,1024)
    const float* b_proj = (const float*)d_in[3];  // (1024,)
    float* out = (float*)d_out;

    cudaFuncSetAttribute(flash_attn_tc, cudaFuncAttributeMaxDynamicSharedMemorySize,
                         FA_SMEM_BYTES);

    qkv_mma<<<dim3(24, 32), 256>>>(x, w_qkv);
    flash_attn_tc<<<dim3(16, 32), 256, FA_SMEM_BYTES>>>();
    proj_mma<<<dim3(8, 32), 256>>>(w_proj, b_proj, out);
}